// round 1
// baseline (speedup 1.0000x reference)
#include <cuda_runtime.h>
#include <cuda_fp16.h>

#define NMAX 50000
#define EMAX 800000
#define CLUS 256
#define FOU1 128
#define FOU2 256
#define HLIN 256
#define OUTP 10
#define GEMM_BLOCKS 148

// ---------------- static scratch (no runtime allocation allowed) ----------------
__device__ float  d_aggx[NMAX * 5];                     // sum of x[src] per dst
__device__ float  d_cnt[NMAX];                          // in-degree count (dst)
__device__ float  d_deg[NMAX];                          // weighted out-degree (src)
__device__ __half d_S16[(size_t)NMAX * CLUS];           // softmax assignment, fp16
__device__ float  d_Y[(size_t)NMAX * FOU1];             // relu features, fp32
__device__ float  d_pool_part[(size_t)GEMM_BLOCKS * CLUS * FOU1];
__device__ float  d_pooled[CLUS * FOU1];
__device__ float  d_ysum[FOU1];                         // sum_i Y[i]
__device__ float  d_mw[FOU2];                           // mean_h @ W2e + b2e
__device__ float  d_g[FOU2];                            // sum_c y2[c]
__device__ float  d_scal[2];                            // [0]=diag sum, [1]=edge sum

// ---------------- K0: zero the accumulators ----------------
__global__ void k0_zero(int n) {
    int tot = n * 5 + 2 * n + FOU1 + FOU2 + 2;
    for (int i = blockIdx.x * blockDim.x + threadIdx.x; i < tot;
         i += gridDim.x * blockDim.x) {
        int j = i;
        if (j < n * 5) { d_aggx[j] = 0.f; continue; } j -= n * 5;
        if (j < n)     { d_cnt[j]  = 0.f; continue; } j -= n;
        if (j < n)     { d_deg[j]  = 0.f; continue; } j -= n;
        if (j < FOU1)  { d_ysum[j] = 0.f; continue; } j -= FOU1;
        if (j < FOU2)  { d_g[j]    = 0.f; continue; } j -= FOU2;
        d_scal[j] = 0.f;
    }
}

// ---------------- K1: edge aggregation (5-dim features, cnt, deg) ----------------
__global__ void k1_edge_agg(const float* __restrict__ x, const int* __restrict__ ei,
                            const float* __restrict__ w, int n, int e) {
    for (int j = blockIdx.x * blockDim.x + threadIdx.x; j < e;
         j += gridDim.x * blockDim.x) {
        int s = ei[j];
        int d = ei[e + j];
        float wv = w[j];
#pragma unroll
        for (int k = 0; k < 5; k++)
            atomicAdd(&d_aggx[d * 5 + k], x[s * 5 + k]);
        atomicAdd(&d_cnt[d], 1.0f);
        atomicAdd(&d_deg[s], wv);
    }
}

// ---------------- K2: fused conv -> softmax S (fp16) / relu Y, diag-sum, ysum ----------------
__global__ __launch_bounds__(256) void k2_node(
    const float* __restrict__ x,
    const float* __restrict__ W1p, const float* __restrict__ R1p, const float* __restrict__ b1p,
    const float* __restrict__ W1e, const float* __restrict__ R1e, const float* __restrict__ b1e,
    int n) {
    __shared__ float ysh[FOU1];
    __shared__ float red[8];
    for (int t = threadIdx.x; t < FOU1; t += blockDim.x) ysh[t] = 0.f;
    __syncthreads();

    int lane = threadIdx.x & 31;
    int wid  = threadIdx.x >> 5;
    int warpsTotal = gridDim.x * 8;
    int gw = blockIdx.x * 8 + wid;

    float yloc[4] = {0.f, 0.f, 0.f, 0.f};
    float dacc = 0.f;

    for (int i = gw; i < n; i += warpsTotal) {
        float xv = 0.f, av = 0.f;
        if (lane < 5) { xv = x[i * 5 + lane]; av = d_aggx[i * 5 + lane]; }
        float cv   = d_cnt[i];
        float degv = d_deg[i];
        float denom = fmaxf(cv, 1.0f);
        float xa[5], aa[5];
#pragma unroll
        for (int k = 0; k < 5; k++) {
            xa[k] = __shfl_sync(0xffffffffu, xv, k);
            aa[k] = __shfl_sync(0xffffffffu, av, k) / denom;
        }
        // s logits: 8 per lane (c = 32*j + lane)
        float sv[8];
#pragma unroll
        for (int j = 0; j < 8; j++) {
            int c = j * 32 + lane;
            float acc = b1p[c];
#pragma unroll
            for (int k = 0; k < 5; k++) {
                acc = fmaf(aa[k], W1p[k * 256 + c], acc);
                acc = fmaf(xa[k], R1p[k * 256 + c], acc);
            }
            sv[j] = acc;
        }
        // softmax over 256 (warp-wide)
        float m = sv[0];
#pragma unroll
        for (int j = 1; j < 8; j++) m = fmaxf(m, sv[j]);
#pragma unroll
        for (int o = 16; o > 0; o >>= 1) m = fmaxf(m, __shfl_xor_sync(0xffffffffu, m, o));
        float sum = 0.f, ev[8];
#pragma unroll
        for (int j = 0; j < 8; j++) { ev[j] = __expf(sv[j] - m); sum += ev[j]; }
#pragma unroll
        for (int o = 16; o > 0; o >>= 1) sum += __shfl_xor_sync(0xffffffffu, sum, o);
        float inv = 1.0f / sum;
        float sq = 0.f;
#pragma unroll
        for (int j = 0; j < 8; j++) {
            float p = ev[j] * inv;
            d_S16[(size_t)i * 256 + j * 32 + lane] = __float2half_rn(p);
            sq = fmaf(p, p, sq);
        }
        if (degv > 0.f) dacc += sq;   // diag_mask * ||S_i||^2
        // y features: 4 per lane
#pragma unroll
        for (int j = 0; j < 4; j++) {
            int c = j * 32 + lane;
            float acc = b1e[c];
#pragma unroll
            for (int k = 0; k < 5; k++) {
                acc = fmaf(aa[k], W1e[k * 128 + c], acc);
                acc = fmaf(xa[k], R1e[k * 128 + c], acc);
            }
            acc = fmaxf(acc, 0.f);
            d_Y[(size_t)i * 128 + c] = acc;
            yloc[j] += acc;
        }
    }
    // reduce diag partial
#pragma unroll
    for (int o = 16; o > 0; o >>= 1) dacc += __shfl_xor_sync(0xffffffffu, dacc, o);
    if (lane == 0) red[wid] = dacc;
#pragma unroll
    for (int j = 0; j < 4; j++) atomicAdd(&ysh[j * 32 + lane], yloc[j]);
    __syncthreads();
    if (threadIdx.x == 0) {
        float t = 0.f;
        for (int k = 0; k < 8; k++) t += red[k];
        atomicAdd(&d_scal[0], t);
    }
    if (threadIdx.x < FOU1) atomicAdd(&d_ysum[threadIdx.x], ysh[threadIdx.x]);
}

// ---------------- K3: pooled = S^T Y, split-K register-tiled, packed f32x2 FMA ----------------
__global__ __launch_bounds__(256, 1) void k3_pool(int n) {
    __shared__ __align__(16) float Ssh[8][CLUS];
    __shared__ __align__(16) float Ysh[8][FOU1];
    int b   = blockIdx.x;
    int per = (n + GEMM_BLOCKS - 1) / GEMM_BLOCKS;
    int lo  = b * per;
    int hi  = min(n, lo + per);
    int tx = threadIdx.x & 15;   // f group: 8 cols
    int ty = threadIdx.x >> 4;   // c group: 16 rows (8 pairs)
    int cbase = ty * 16;
    int fbase = tx * 8;

    unsigned long long acc[8][8];
#pragma unroll
    for (int p = 0; p < 8; p++)
#pragma unroll
        for (int q = 0; q < 8; q++) acc[p][q] = 0ull;

    for (int i0 = lo; i0 < hi; i0 += 8) {
        __syncthreads();
        int nb = hi - i0; if (nb > 8) nb = 8;
        for (int r = 0; r < 8; r++) {
            if (r < nb) {
                Ssh[r][threadIdx.x] = __half2float(d_S16[(size_t)(i0 + r) * 256 + threadIdx.x]);
                if (threadIdx.x < FOU1)
                    Ysh[r][threadIdx.x] = d_Y[(size_t)(i0 + r) * 128 + threadIdx.x];
            } else {
                Ssh[r][threadIdx.x] = 0.f;
                if (threadIdx.x < FOU1) Ysh[r][threadIdx.x] = 0.f;
            }
        }
        __syncthreads();
#pragma unroll
        for (int r = 0; r < 8; r++) {
            const ulonglong2* sp2 = (const ulonglong2*)&Ssh[r][cbase];
            ulonglong2 a0 = sp2[0], a1 = sp2[1], a2 = sp2[2], a3 = sp2[3];
            unsigned long long sp[8] = {a0.x, a0.y, a1.x, a1.y, a2.x, a2.y, a3.x, a3.y};
            float4 y0 = *(const float4*)&Ysh[r][fbase];
            float4 y1 = *(const float4*)&Ysh[r][fbase + 4];
            float yv[8] = {y0.x, y0.y, y0.z, y0.w, y1.x, y1.y, y1.z, y1.w};
#pragma unroll
            for (int q = 0; q < 8; q++) {
                unsigned long long yd;
                asm("mov.b64 %0, {%1, %1};" : "=l"(yd) : "f"(yv[q]));
#pragma unroll
                for (int p = 0; p < 8; p++) {
                    asm("fma.rn.f32x2 %0, %1, %2, %0;"
                        : "+l"(acc[p][q]) : "l"(sp[p]), "l"(yd));
                }
            }
        }
    }
    float* out = &d_pool_part[(size_t)b * CLUS * FOU1];
#pragma unroll
    for (int p = 0; p < 8; p++) {
#pragma unroll
        for (int q = 0; q < 8; q++) {
            float vx, vy;
            asm("mov.b64 {%0, %1}, %2;" : "=f"(vx), "=f"(vy) : "l"(acc[p][q]));
            out[(size_t)(cbase + 2 * p)     * FOU1 + fbase + q] = vx;
            out[(size_t)(cbase + 2 * p + 1) * FOU1 + fbase + q] = vy;
        }
    }
}

// ---------------- K4: reduce split-K partials ----------------
__global__ void k4_reduce() {
    int idx = blockIdx.x * blockDim.x + threadIdx.x;
    if (idx < CLUS * FOU1) {
        float s = 0.f;
        for (int p = 0; p < GEMM_BLOCKS; p++)
            s += d_pool_part[(size_t)p * CLUS * FOU1 + idx];
        d_pooled[idx] = s;
    }
}

// ---------------- K5: edge SDDMM  sum_e c_e * <S[src], S[dst]>  (fp16 S) ----------------
__global__ __launch_bounds__(256) void k5_edge(const int* __restrict__ ei,
                                               const float* __restrict__ w, int e) {
    __shared__ float red[8];
    int lane = threadIdx.x & 31;
    int wid  = threadIdx.x >> 5;
    int gw = blockIdx.x * 8 + wid;
    int tw = gridDim.x * 8;
    float acc = 0.f;
    for (int j = gw; j < e; j += tw) {
        int s = ei[j];
        int d = ei[e + j];
        float ds = d_deg[s], dd = d_deg[d];
        float c = w[j];
        c = (ds > 0.f) ? c * rsqrtf(ds) : 0.f;
        c = (dd > 0.f) ? c * rsqrtf(dd) : 0.f;
        const uint4* ps = (const uint4*)(&d_S16[(size_t)s * 256]);
        const uint4* pd = (const uint4*)(&d_S16[(size_t)d * 256]);
        uint4 ua = ps[lane];
        uint4 ub = pd[lane];
        const __half2* ha = (const __half2*)&ua;
        const __half2* hb = (const __half2*)&ub;
        float dot = 0.f;
#pragma unroll
        for (int q = 0; q < 4; q++) {
            float2 fa = __half22float2(ha[q]);
            float2 fb = __half22float2(hb[q]);
            dot = fmaf(fa.x, fb.x, dot);
            dot = fmaf(fa.y, fb.y, dot);
        }
        acc = fmaf(c, dot, acc);
    }
#pragma unroll
    for (int o = 16; o > 0; o >>= 1) acc += __shfl_xor_sync(0xffffffffu, acc, o);
    if (lane == 0) red[wid] = acc;
    __syncthreads();
    if (threadIdx.x == 0) {
        float t = 0.f;
        for (int k = 0; k < 8; k++) t += red[k];
        atomicAdd(&d_scal[1], t);
    }
}

// ---------------- K5b: mw = mean_h @ W2e + b2e ----------------
__global__ void k_mw(const float* __restrict__ W2e, const float* __restrict__ b2e) {
    int k = threadIdx.x;   // 256 threads
    float acc = b2e[k];
    for (int f = 0; f < FOU1; f++)
        acc = fmaf(d_ysum[f] * (1.0f / 256.0f), W2e[f * 256 + k], acc);
    d_mw[k] = acc;
}

// ---------------- K6: g[k] = sum_c relu(mw[k] + pooled[c] . R2e[:,k]) ----------------
__global__ __launch_bounds__(256) void k6_y2(const float* __restrict__ R2e) {
    __shared__ float prow[FOU1];
    int c = blockIdx.x;
    if (threadIdx.x < FOU1) prow[threadIdx.x] = d_pooled[c * FOU1 + threadIdx.x];
    __syncthreads();
    int k = threadIdx.x;
    float acc = d_mw[k];
#pragma unroll 4
    for (int f = 0; f < FOU1; f++)
        acc = fmaf(prow[f], R2e[f * 256 + k], acc);
    acc = fmaxf(acc, 0.f);
    atomicAdd(&d_g[k], acc);
}

// ---------------- K7: MLP head + log_softmax + reg1 ----------------
__global__ __launch_bounds__(256) void k7_final(
    const float* __restrict__ Wl1, const float* __restrict__ bl1,
    const float* __restrict__ Wl2, const float* __restrict__ bl2,
    float* __restrict__ out, int n, int out_size) {
    __shared__ float gsh[FOU2];
    __shared__ float h1[HLIN];
    __shared__ float lg[OUTP];
    int t = threadIdx.x;
    gsh[t] = d_g[t];
    __syncthreads();
    float acc = bl1[t];
    for (int k = 0; k < FOU2; k++) acc = fmaf(gsh[k], Wl1[k * HLIN + t], acc);
    h1[t] = fmaxf(acc, 0.f);
    __syncthreads();
    if (t < OUTP) {
        float a2 = bl2[t];
        for (int j = 0; j < HLIN; j++) a2 = fmaf(h1[j], Wl2[j * OUTP + t], a2);
        lg[t] = a2;
    }
    __syncthreads();
    if (t == 0) {
        float m = lg[0];
        for (int o = 1; o < OUTP; o++) m = fmaxf(m, lg[o]);
        float s = 0.f;
        for (int o = 0; o < OUTP; o++) s += expf(lg[o] - m);
        float lse = m + logf(s);
        for (int o = 0; o < OUTP; o++) out[o] = lg[o] - lse;
        if (out_size > OUTP) out[OUTP] = (d_scal[0] - d_scal[1]) / (float)n;
    }
}

// ---------------- launch ----------------
extern "C" void kernel_launch(void* const* d_in, const int* in_sizes, int n_in,
                              void* d_out, int out_size) {
    const float* x   = (const float*)d_in[0];
    const int*   ei  = (const int*)d_in[1];
    const float* wht = (const float*)d_in[2];
    const float* W1p = (const float*)d_in[3];
    const float* R1p = (const float*)d_in[4];
    const float* b1p = (const float*)d_in[5];
    const float* W1e = (const float*)d_in[6];
    const float* R1e = (const float*)d_in[7];
    const float* b1e = (const float*)d_in[8];
    // d_in[9..11] = W2p, R2p, b2p: dead code (softmax over size-1 axis == 1)
    const float* W2e = (const float*)d_in[12];
    const float* b2e = (const float*)d_in[14];
    const float* R2e = (const float*)d_in[13];
    const float* Wl1 = (const float*)d_in[15];
    const float* bl1 = (const float*)d_in[16];
    const float* Wl2 = (const float*)d_in[17];
    const float* bl2 = (const float*)d_in[18];

    int n = in_sizes[0] / 5;
    int e = in_sizes[2];

    k0_zero<<<512, 256>>>(n);
    k1_edge_agg<<<(e + 255) / 256, 256>>>(x, ei, wht, n, e);
    k2_node<<<592, 256>>>(x, W1p, R1p, b1p, W1e, R1e, b1e, n);
    k3_pool<<<GEMM_BLOCKS, 256>>>(n);
    k4_reduce<<<128, 256>>>();
    k5_edge<<<1184, 256>>>(ei, wht, e);
    k_mw<<<1, 256>>>(W2e, b2e);
    k6_y2<<<CLUS, 256>>>(R2e);
    k7_final<<<1, 256>>>(Wl1, bl1, Wl2, bl2, (float*)d_out, n, out_size);
}

// round 2
// speedup vs baseline: 2.0326x; 2.0326x over previous
#include <cuda_runtime.h>
#include <cuda_fp16.h>

#define NMAX 50000
#define EMAX 800000
#define CLUS 256
#define FOU1 128
#define FOU2 256
#define HLIN 256
#define OUTP 10
#define KSPLIT 74

// ---------------- static scratch (no runtime allocation allowed) ----------------
__device__ float  d_aggx[NMAX * 5];                     // sum of x[src] per dst
__device__ float  d_cnt[NMAX];                          // in-degree count (dst)
__device__ float  d_deg[NMAX];                          // weighted out-degree (src)
__device__ __half d_S16[(size_t)NMAX * CLUS];           // softmax assignment, fp16
__device__ __half d_Y16[(size_t)NMAX * FOU1];           // relu features, fp16
__device__ float  d_pool_part[(size_t)KSPLIT * CLUS * FOU1];
__device__ float  d_pooled[CLUS * FOU1];
__device__ float  d_ysum[FOU1];                         // sum_i Y[i] (fp32 exact path)
__device__ float  d_mw[FOU2];                           // mean_h @ W2e + b2e
__device__ float  d_g[FOU2];                            // sum_c y2[c]
__device__ float  d_scal[2];                            // [0]=diag sum, [1]=edge sum

// ---------------- K0: zero the accumulators ----------------
__global__ void k0_zero(int n) {
    int tot = n * 5 + 2 * n + FOU1 + FOU2 + 2;
    for (int i = blockIdx.x * blockDim.x + threadIdx.x; i < tot;
         i += gridDim.x * blockDim.x) {
        int j = i;
        if (j < n * 5) { d_aggx[j] = 0.f; continue; } j -= n * 5;
        if (j < n)     { d_cnt[j]  = 0.f; continue; } j -= n;
        if (j < n)     { d_deg[j]  = 0.f; continue; } j -= n;
        if (j < FOU1)  { d_ysum[j] = 0.f; continue; } j -= FOU1;
        if (j < FOU2)  { d_g[j]    = 0.f; continue; } j -= FOU2;
        d_scal[j] = 0.f;
    }
}

// ---------------- K1: edge aggregation (5-dim features, cnt, deg) ----------------
__global__ void k1_edge_agg(const float* __restrict__ x, const int* __restrict__ ei,
                            const float* __restrict__ w, int n, int e) {
    for (int j = blockIdx.x * blockDim.x + threadIdx.x; j < e;
         j += gridDim.x * blockDim.x) {
        int s = ei[j];
        int d = ei[e + j];
        float wv = w[j];
#pragma unroll
        for (int k = 0; k < 5; k++)
            atomicAdd(&d_aggx[d * 5 + k], x[s * 5 + k]);
        atomicAdd(&d_cnt[d], 1.0f);
        atomicAdd(&d_deg[s], wv);
    }
}

// ---------------- K2: fused conv -> softmax S (fp16) / relu Y (fp16), diag-sum, ysum ----------------
__global__ __launch_bounds__(256) void k2_node(
    const float* __restrict__ x,
    const float* __restrict__ W1p, const float* __restrict__ R1p, const float* __restrict__ b1p,
    const float* __restrict__ W1e, const float* __restrict__ R1e, const float* __restrict__ b1e,
    int n) {
    __shared__ float ysh[FOU1];
    __shared__ float red[8];
    for (int t = threadIdx.x; t < FOU1; t += blockDim.x) ysh[t] = 0.f;
    __syncthreads();

    int lane = threadIdx.x & 31;
    int wid  = threadIdx.x >> 5;
    int warpsTotal = gridDim.x * 8;
    int gw = blockIdx.x * 8 + wid;

    float yloc[4] = {0.f, 0.f, 0.f, 0.f};
    float dacc = 0.f;

    for (int i = gw; i < n; i += warpsTotal) {
        float xv = 0.f, av = 0.f;
        if (lane < 5) { xv = x[i * 5 + lane]; av = d_aggx[i * 5 + lane]; }
        float cv   = d_cnt[i];
        float degv = d_deg[i];
        float denom = fmaxf(cv, 1.0f);
        float xa[5], aa[5];
#pragma unroll
        for (int k = 0; k < 5; k++) {
            xa[k] = __shfl_sync(0xffffffffu, xv, k);
            aa[k] = __shfl_sync(0xffffffffu, av, k) / denom;
        }
        float sv[8];
#pragma unroll
        for (int j = 0; j < 8; j++) {
            int c = j * 32 + lane;
            float acc = b1p[c];
#pragma unroll
            for (int k = 0; k < 5; k++) {
                acc = fmaf(aa[k], W1p[k * 256 + c], acc);
                acc = fmaf(xa[k], R1p[k * 256 + c], acc);
            }
            sv[j] = acc;
        }
        float m = sv[0];
#pragma unroll
        for (int j = 1; j < 8; j++) m = fmaxf(m, sv[j]);
#pragma unroll
        for (int o = 16; o > 0; o >>= 1) m = fmaxf(m, __shfl_xor_sync(0xffffffffu, m, o));
        float sum = 0.f, ev[8];
#pragma unroll
        for (int j = 0; j < 8; j++) { ev[j] = __expf(sv[j] - m); sum += ev[j]; }
#pragma unroll
        for (int o = 16; o > 0; o >>= 1) sum += __shfl_xor_sync(0xffffffffu, sum, o);
        float inv = 1.0f / sum;
        float sq = 0.f;
#pragma unroll
        for (int j = 0; j < 8; j++) {
            float p = ev[j] * inv;
            d_S16[(size_t)i * 256 + j * 32 + lane] = __float2half_rn(p);
            sq = fmaf(p, p, sq);
        }
        if (degv > 0.f) dacc += sq;
#pragma unroll
        for (int j = 0; j < 4; j++) {
            int c = j * 32 + lane;
            float acc = b1e[c];
#pragma unroll
            for (int k = 0; k < 5; k++) {
                acc = fmaf(aa[k], W1e[k * 128 + c], acc);
                acc = fmaf(xa[k], R1e[k * 128 + c], acc);
            }
            acc = fmaxf(acc, 0.f);
            d_Y16[(size_t)i * 128 + c] = __float2half_rn(acc);
            yloc[j] += acc;
        }
    }
#pragma unroll
    for (int o = 16; o > 0; o >>= 1) dacc += __shfl_xor_sync(0xffffffffu, dacc, o);
    if (lane == 0) red[wid] = dacc;
#pragma unroll
    for (int j = 0; j < 4; j++) atomicAdd(&ysh[j * 32 + lane], yloc[j]);
    __syncthreads();
    if (threadIdx.x == 0) {
        float t = 0.f;
        for (int k = 0; k < 8; k++) t += red[k];
        atomicAdd(&d_scal[0], t);
    }
    if (threadIdx.x < FOU1) atomicAdd(&d_ysum[threadIdx.x], ysh[threadIdx.x]);
}

// ---------------- K3: pooled = S^T Y via mma.sync m16n8k16 (fp16 x fp16 -> fp32) ----------------
#define CHUNK 32
#define APITCH 136   // 128 halves + 8 pad (pitch 272B -> conflict-free ldmatrix.trans)

__device__ __forceinline__ unsigned shaddr(const void* p) {
    return (unsigned)__cvta_generic_to_shared(p);
}
__device__ __forceinline__ void ldsm4t(unsigned* r, unsigned addr) {
    asm volatile("ldmatrix.sync.aligned.m8n8.x4.trans.shared.b16 {%0,%1,%2,%3}, [%4];"
                 : "=r"(r[0]), "=r"(r[1]), "=r"(r[2]), "=r"(r[3]) : "r"(addr));
}
__device__ __forceinline__ void mma16816(float* c, const unsigned* a, const unsigned* b) {
    asm volatile("mma.sync.aligned.m16n8k16.row.col.f32.f16.f16.f32 "
                 "{%0,%1,%2,%3}, {%4,%5,%6,%7}, {%8,%9}, {%0,%1,%2,%3};"
                 : "+f"(c[0]), "+f"(c[1]), "+f"(c[2]), "+f"(c[3])
                 : "r"(a[0]), "r"(a[1]), "r"(a[2]), "r"(a[3]), "r"(b[0]), "r"(b[1]));
}

__global__ __launch_bounds__(256) void k3_pool(int n) {
    __shared__ __align__(16) __half A_s[CHUNK][APITCH];   // S chunk  [i][c-half]
    __shared__ __align__(16) __half B_s[CHUNK][APITCH];   // Y chunk  [i][f]
    int b     = blockIdx.x;
    int chalf = b & 1;
    int kb    = b >> 1;
    int per   = (n + KSPLIT - 1) / KSPLIT;
    int lo    = kb * per;
    int hi    = min(n, lo + per);

    int tid  = threadIdx.x;
    int lane = tid & 31;
    int wid  = tid >> 5;
    int m_base  = (wid >> 1) * 32;    // warp m-tile (within 128-c half)
    int f_basew = (wid & 1) * 64;     // warp n-tile

    float acc[2][8][4];
#pragma unroll
    for (int p = 0; p < 2; p++)
#pragma unroll
        for (int q = 0; q < 8; q++)
#pragma unroll
            for (int v = 0; v < 4; v++) acc[p][q][v] = 0.f;

    for (int i0 = lo; i0 < hi; i0 += CHUNK) {
        __syncthreads();
        // load 32 rows of S(c-half) and Y as half2, coalesced, layout-preserving
#pragma unroll
        for (int rep = 0; rep < 8; rep++) {
            int e2    = rep * 256 + tid;        // 2048 half2 = 32 rows x 64 half2
            int i_loc = e2 >> 6;
            int c2    = e2 & 63;
            int g     = i0 + i_loc;
            unsigned va = 0u, vb = 0u;
            if (g < hi) {
                va = *(const unsigned*)&d_S16[(size_t)g * 256 + chalf * 128 + 2 * c2];
                vb = *(const unsigned*)&d_Y16[(size_t)g * 128 + 2 * c2];
            }
            *(unsigned*)&A_s[i_loc][2 * c2] = va;
            *(unsigned*)&B_s[i_loc][2 * c2] = vb;
        }
        __syncthreads();
#pragma unroll
        for (int t = 0; t < 2; t++) {
            // A fragments: smem is [k][m]; ldmatrix.trans -> A row-major frags
            int krA = t * 16 + (lane & 7) + ((lane >> 4) << 3);   // bit4 -> k+8
            unsigned aaddr = shaddr(&A_s[krA][m_base + ((lane >> 3) & 1) * 8]); // bit3 -> m+8
            unsigned afrag[2][4];
            ldsm4t(afrag[0], aaddr);
            ldsm4t(afrag[1], aaddr + 32);     // +16 m-halves = next m16 tile
            // B fragments: smem is [k][n]; .trans -> B col-major frags
            int krB = t * 16 + (lane & 7) + (lane & 8);           // bit3 -> k+8
            unsigned baddr = shaddr(&B_s[krB][f_basew + ((lane >> 4) & 1) * 8]); // bit4 -> n+8
            unsigned bfrag[4][4];
#pragma unroll
            for (int gq = 0; gq < 4; gq++)
                ldsm4t(bfrag[gq], baddr + gq * 32);   // +16 f per group
#pragma unroll
            for (int p = 0; p < 2; p++)
#pragma unroll
                for (int q = 0; q < 8; q++)
                    mma16816(acc[p][q], afrag[p], &bfrag[q >> 1][(q & 1) * 2]);
        }
    }

    float* part = &d_pool_part[(size_t)kb * CLUS * FOU1];
    int r    = lane >> 2;
    int col2 = (lane & 3) * 2;
#pragma unroll
    for (int p = 0; p < 2; p++) {
#pragma unroll
        for (int q = 0; q < 8; q++) {
            int cg = chalf * 128 + m_base + p * 16 + r;
            int f  = f_basew + q * 8 + col2;
            *(float2*)&part[(size_t)cg * FOU1 + f]       = make_float2(acc[p][q][0], acc[p][q][1]);
            *(float2*)&part[(size_t)(cg + 8) * FOU1 + f] = make_float2(acc[p][q][2], acc[p][q][3]);
        }
    }
}

// ---------------- K4: reduce split-K partials ----------------
__global__ void k4_reduce() {
    int idx = blockIdx.x * blockDim.x + threadIdx.x;
    if (idx < CLUS * FOU1) {
        float s = 0.f;
        for (int p = 0; p < KSPLIT; p++)
            s += d_pool_part[(size_t)p * CLUS * FOU1 + idx];
        d_pooled[idx] = s;
    }
}

// ---------------- K5: edge SDDMM  sum_e c_e * <S[src], S[dst]>  (fp16 S) ----------------
__global__ __launch_bounds__(256) void k5_edge(const int* __restrict__ ei,
                                               const float* __restrict__ w, int e) {
    __shared__ float red[8];
    int lane = threadIdx.x & 31;
    int wid  = threadIdx.x >> 5;
    int gw = blockIdx.x * 8 + wid;
    int tw = gridDim.x * 8;
    float acc = 0.f;
    for (int j = gw; j < e; j += tw) {
        int s = ei[j];
        int d = ei[e + j];
        float ds = d_deg[s], dd = d_deg[d];
        float c = w[j];
        c = (ds > 0.f) ? c * rsqrtf(ds) : 0.f;
        c = (dd > 0.f) ? c * rsqrtf(dd) : 0.f;
        const uint4* ps = (const uint4*)(&d_S16[(size_t)s * 256]);
        const uint4* pd = (const uint4*)(&d_S16[(size_t)d * 256]);
        uint4 ua = ps[lane];
        uint4 ub = pd[lane];
        const __half2* ha = (const __half2*)&ua;
        const __half2* hb = (const __half2*)&ub;
        float dot = 0.f;
#pragma unroll
        for (int q = 0; q < 4; q++) {
            float2 fa = __half22float2(ha[q]);
            float2 fb = __half22float2(hb[q]);
            dot = fmaf(fa.x, fb.x, dot);
            dot = fmaf(fa.y, fb.y, dot);
        }
        acc = fmaf(c, dot, acc);
    }
#pragma unroll
    for (int o = 16; o > 0; o >>= 1) acc += __shfl_xor_sync(0xffffffffu, acc, o);
    if (lane == 0) red[wid] = acc;
    __syncthreads();
    if (threadIdx.x == 0) {
        float t = 0.f;
        for (int k = 0; k < 8; k++) t += red[k];
        atomicAdd(&d_scal[1], t);
    }
}

// ---------------- K5b: mw = mean_h @ W2e + b2e ----------------
__global__ void k_mw(const float* __restrict__ W2e, const float* __restrict__ b2e) {
    int k = threadIdx.x;   // 256 threads
    float acc = b2e[k];
    for (int f = 0; f < FOU1; f++)
        acc = fmaf(d_ysum[f] * (1.0f / 256.0f), W2e[f * 256 + k], acc);
    d_mw[k] = acc;
}

// ---------------- K6: g[k] = sum_c relu(mw[k] + pooled[c] . R2e[:,k]) ----------------
__global__ __launch_bounds__(256) void k6_y2(const float* __restrict__ R2e) {
    __shared__ float prow[FOU1];
    int c = blockIdx.x;
    if (threadIdx.x < FOU1) prow[threadIdx.x] = d_pooled[c * FOU1 + threadIdx.x];
    __syncthreads();
    int k = threadIdx.x;
    float acc = d_mw[k];
#pragma unroll 4
    for (int f = 0; f < FOU1; f++)
        acc = fmaf(prow[f], R2e[f * 256 + k], acc);
    acc = fmaxf(acc, 0.f);
    atomicAdd(&d_g[k], acc);
}

// ---------------- K7: MLP head + log_softmax + reg1 ----------------
__global__ __launch_bounds__(256) void k7_final(
    const float* __restrict__ Wl1, const float* __restrict__ bl1,
    const float* __restrict__ Wl2, const float* __restrict__ bl2,
    float* __restrict__ out, int n, int out_size) {
    __shared__ float gsh[FOU2];
    __shared__ float h1[HLIN];
    __shared__ float lg[OUTP];
    int t = threadIdx.x;
    gsh[t] = d_g[t];
    __syncthreads();
    float acc = bl1[t];
    for (int k = 0; k < FOU2; k++) acc = fmaf(gsh[k], Wl1[k * HLIN + t], acc);
    h1[t] = fmaxf(acc, 0.f);
    __syncthreads();
    if (t < OUTP) {
        float a2 = bl2[t];
        for (int j = 0; j < HLIN; j++) a2 = fmaf(h1[j], Wl2[j * OUTP + t], a2);
        lg[t] = a2;
    }
    __syncthreads();
    if (t == 0) {
        float m = lg[0];
        for (int o = 1; o < OUTP; o++) m = fmaxf(m, lg[o]);
        float s = 0.f;
        for (int o = 0; o < OUTP; o++) s += expf(lg[o] - m);
        float lse = m + logf(s);
        for (int o = 0; o < OUTP; o++) out[o] = lg[o] - lse;
        if (out_size > OUTP) out[OUTP] = (d_scal[0] - d_scal[1]) / (float)n;
    }
}

// ---------------- launch ----------------
extern "C" void kernel_launch(void* const* d_in, const int* in_sizes, int n_in,
                              void* d_out, int out_size) {
    const float* x   = (const float*)d_in[0];
    const int*   ei  = (const int*)d_in[1];
    const float* wht = (const float*)d_in[2];
    const float* W1p = (const float*)d_in[3];
    const float* R1p = (const float*)d_in[4];
    const float* b1p = (const float*)d_in[5];
    const float* W1e = (const float*)d_in[6];
    const float* R1e = (const float*)d_in[7];
    const float* b1e = (const float*)d_in[8];
    // d_in[9..11] = W2p, R2p, b2p: dead code (softmax over size-1 axis == 1)
    const float* W2e = (const float*)d_in[12];
    const float* R2e = (const float*)d_in[13];
    const float* b2e = (const float*)d_in[14];
    const float* Wl1 = (const float*)d_in[15];
    const float* bl1 = (const float*)d_in[16];
    const float* Wl2 = (const float*)d_in[17];
    const float* bl2 = (const float*)d_in[18];

    int n = in_sizes[0] / 5;
    int e = in_sizes[2];

    k0_zero<<<512, 256>>>(n);
    k1_edge_agg<<<(e + 255) / 256, 256>>>(x, ei, wht, n, e);
    k2_node<<<592, 256>>>(x, W1p, R1p, b1p, W1e, R1e, b1e, n);
    k3_pool<<<2 * KSPLIT, 256>>>(n);
    k4_reduce<<<128, 256>>>();
    k5_edge<<<1184, 256>>>(ei, wht, e);
    k_mw<<<1, 256>>>(W2e, b2e);
    k6_y2<<<CLUS, 256>>>(R2e);
    k7_final<<<1, 256>>>(Wl1, bl1, Wl2, bl2, (float*)d_out, n, out_size);
}

// round 3
// speedup vs baseline: 2.1391x; 1.0524x over previous
#include <cuda_runtime.h>
#include <cuda_fp16.h>
#include <cuda_fp8.h>

#define NMAX 50000
#define EMAX 800000
#define CLUS 256
#define FOU1 128
#define FOU2 256
#define HLIN 256
#define OUTP 10
#define KSPLIT 148

// ---------------- static scratch (no runtime allocation allowed) ----------------
__device__ __align__(32) float d_agg[NMAX * 8];         // [0..4]=sum x[src], [5]=cnt
__device__ float  d_deg[NMAX];                          // weighted out-degree (src)
__device__ __half d_S16[(size_t)NMAX * CLUS];           // softmax assignment, fp16 (for GEMM)
__device__ unsigned char d_R8[(size_t)NMAX * CLUS];     // fp8 e4m3 of 128*(S - 1/256)
__device__ __half d_Y16[(size_t)NMAX * FOU1];           // relu features, fp16
__device__ float  d_pooled[CLUS * FOU1];                // atomically accumulated
__device__ float  d_ysum[FOU1];                         // sum_i Y[i]
__device__ float  d_mw[FOU2];                           // mean_h @ W2e + b2e
__device__ float  d_g[FOU2];                            // sum_c y2[c]
__device__ float  d_scal[3];                            // [0]=diag, [1]=edge_r(scaled), [2]=edge_c

// ---------------- K0: zero the accumulators ----------------
__global__ void k0_zero(int n) {
    int tot = n * 8 + n + CLUS * FOU1 + FOU1 + FOU2 + 3;
    for (int i = blockIdx.x * blockDim.x + threadIdx.x; i < tot;
         i += gridDim.x * blockDim.x) {
        int j = i;
        if (j < n * 8)       { d_agg[j]    = 0.f; continue; } j -= n * 8;
        if (j < n)           { d_deg[j]    = 0.f; continue; } j -= n;
        if (j < CLUS * FOU1) { d_pooled[j] = 0.f; continue; } j -= CLUS * FOU1;
        if (j < FOU1)        { d_ysum[j]   = 0.f; continue; } j -= FOU1;
        if (j < FOU2)        { d_g[j]      = 0.f; continue; } j -= FOU2;
        d_scal[j] = 0.f;
    }
}

// ---------------- K1: edge aggregation with vectorized red ----------------
__global__ void k1_edge_agg(const float* __restrict__ x, const int* __restrict__ ei,
                            const float* __restrict__ w, int n, int e) {
    for (int j = blockIdx.x * blockDim.x + threadIdx.x; j < e;
         j += gridDim.x * blockDim.x) {
        int s = ei[j];
        int d = ei[e + j];
        float wv = w[j];
        float x0 = __ldg(&x[s * 5 + 0]);
        float x1 = __ldg(&x[s * 5 + 1]);
        float x2 = __ldg(&x[s * 5 + 2]);
        float x3 = __ldg(&x[s * 5 + 3]);
        float x4 = __ldg(&x[s * 5 + 4]);
        float* base = &d_agg[(size_t)d * 8];
        float one = 1.0f;
        asm volatile("red.global.add.v4.f32 [%0], {%1,%2,%3,%4};"
                     :: "l"(base), "f"(x0), "f"(x1), "f"(x2), "f"(x3) : "memory");
        asm volatile("red.global.add.v2.f32 [%0], {%1,%2};"
                     :: "l"(base + 4), "f"(x4), "f"(one) : "memory");
        atomicAdd(&d_deg[s], wv);
    }
}

// ---------------- K2: fused conv -> softmax S (fp16 + fp8 residual) / relu Y ----------------
__global__ __launch_bounds__(256) void k2_node(
    const float* __restrict__ x,
    const float* __restrict__ W1p, const float* __restrict__ R1p, const float* __restrict__ b1p,
    const float* __restrict__ W1e, const float* __restrict__ R1e, const float* __restrict__ b1e,
    int n) {
    __shared__ float ysh[FOU1];
    __shared__ float red[8];
    for (int t = threadIdx.x; t < FOU1; t += blockDim.x) ysh[t] = 0.f;
    __syncthreads();

    int lane = threadIdx.x & 31;
    int wid  = threadIdx.x >> 5;
    int warpsTotal = gridDim.x * 8;
    int gw = blockIdx.x * 8 + wid;

    float yloc[4] = {0.f, 0.f, 0.f, 0.f};
    float dacc = 0.f;

    for (int i = gw; i < n; i += warpsTotal) {
        float xv = 0.f, av = 0.f;
        if (lane < 5) { xv = x[i * 5 + lane]; }
        if (lane < 6) { av = d_agg[(size_t)i * 8 + lane]; }
        float cv   = __shfl_sync(0xffffffffu, av, 5);
        float degv = d_deg[i];
        float denom = fmaxf(cv, 1.0f);
        float xa[5], aa[5];
#pragma unroll
        for (int k = 0; k < 5; k++) {
            xa[k] = __shfl_sync(0xffffffffu, xv, k);
            aa[k] = __shfl_sync(0xffffffffu, av, k) / denom;
        }
        float sv[8];
#pragma unroll
        for (int j = 0; j < 8; j++) {
            int c = j * 32 + lane;
            float acc = b1p[c];
#pragma unroll
            for (int k = 0; k < 5; k++) {
                acc = fmaf(aa[k], W1p[k * 256 + c], acc);
                acc = fmaf(xa[k], R1p[k * 256 + c], acc);
            }
            sv[j] = acc;
        }
        float m = sv[0];
#pragma unroll
        for (int j = 1; j < 8; j++) m = fmaxf(m, sv[j]);
#pragma unroll
        for (int o = 16; o > 0; o >>= 1) m = fmaxf(m, __shfl_xor_sync(0xffffffffu, m, o));
        float sum = 0.f, ev[8];
#pragma unroll
        for (int j = 0; j < 8; j++) { ev[j] = __expf(sv[j] - m); sum += ev[j]; }
#pragma unroll
        for (int o = 16; o > 0; o >>= 1) sum += __shfl_xor_sync(0xffffffffu, sum, o);
        float inv = 1.0f / sum;
        float sq = 0.f;
#pragma unroll
        for (int j = 0; j < 8; j++) {
            float p = ev[j] * inv;
            d_S16[(size_t)i * 256 + j * 32 + lane] = __float2half_rn(p);
            d_R8[(size_t)i * 256 + j * 32 + lane] =
                __nv_cvt_float_to_fp8((p - 0.00390625f) * 128.0f, __NV_SATFINITE, __NV_E4M3);
            sq = fmaf(p, p, sq);
        }
        if (degv > 0.f) dacc += sq;
#pragma unroll
        for (int j = 0; j < 4; j++) {
            int c = j * 32 + lane;
            float acc = b1e[c];
#pragma unroll
            for (int k = 0; k < 5; k++) {
                acc = fmaf(aa[k], W1e[k * 128 + c], acc);
                acc = fmaf(xa[k], R1e[k * 128 + c], acc);
            }
            acc = fmaxf(acc, 0.f);
            d_Y16[(size_t)i * 128 + c] = __float2half_rn(acc);
            yloc[j] += acc;
        }
    }
#pragma unroll
    for (int o = 16; o > 0; o >>= 1) dacc += __shfl_xor_sync(0xffffffffu, dacc, o);
    if (lane == 0) red[wid] = dacc;
#pragma unroll
    for (int j = 0; j < 4; j++) atomicAdd(&ysh[j * 32 + lane], yloc[j]);
    __syncthreads();
    if (threadIdx.x == 0) {
        float t = 0.f;
        for (int k = 0; k < 8; k++) t += red[k];
        atomicAdd(&d_scal[0], t);
    }
    if (threadIdx.x < FOU1) atomicAdd(&d_ysum[threadIdx.x], ysh[threadIdx.x]);
}

// ---------------- K3: pooled += S^T Y via mma.sync m16n8k16, atomic epilogue ----------------
#define CHUNK 32
#define APITCH 136

__device__ __forceinline__ unsigned shaddr(const void* p) {
    return (unsigned)__cvta_generic_to_shared(p);
}
__device__ __forceinline__ void ldsm4t(unsigned* r, unsigned addr) {
    asm volatile("ldmatrix.sync.aligned.m8n8.x4.trans.shared.b16 {%0,%1,%2,%3}, [%4];"
                 : "=r"(r[0]), "=r"(r[1]), "=r"(r[2]), "=r"(r[3]) : "r"(addr));
}
__device__ __forceinline__ void mma16816(float* c, const unsigned* a, const unsigned* b) {
    asm volatile("mma.sync.aligned.m16n8k16.row.col.f32.f16.f16.f32 "
                 "{%0,%1,%2,%3}, {%4,%5,%6,%7}, {%8,%9}, {%0,%1,%2,%3};"
                 : "+f"(c[0]), "+f"(c[1]), "+f"(c[2]), "+f"(c[3])
                 : "r"(a[0]), "r"(a[1]), "r"(a[2]), "r"(a[3]), "r"(b[0]), "r"(b[1]));
}

__global__ __launch_bounds__(256) void k3_pool(int n) {
    __shared__ __align__(16) __half A_s[CHUNK][APITCH];   // S chunk  [i][c-half]
    __shared__ __align__(16) __half B_s[CHUNK][APITCH];   // Y chunk  [i][f]
    int b     = blockIdx.x;
    int chalf = b & 1;
    int kb    = b >> 1;
    int per   = (n + KSPLIT - 1) / KSPLIT;
    int lo    = kb * per;
    int hi    = min(n, lo + per);

    int tid  = threadIdx.x;
    int lane = tid & 31;
    int wid  = tid >> 5;
    int m_base  = (wid >> 1) * 32;
    int f_basew = (wid & 1) * 64;

    float acc[2][8][4];
#pragma unroll
    for (int p = 0; p < 2; p++)
#pragma unroll
        for (int q = 0; q < 8; q++)
#pragma unroll
            for (int v = 0; v < 4; v++) acc[p][q][v] = 0.f;

    for (int i0 = lo; i0 < hi; i0 += CHUNK) {
        __syncthreads();
#pragma unroll
        for (int rep = 0; rep < 8; rep++) {
            int e2    = rep * 256 + tid;
            int i_loc = e2 >> 6;
            int c2    = e2 & 63;
            int g     = i0 + i_loc;
            unsigned va = 0u, vb = 0u;
            if (g < hi) {
                va = *(const unsigned*)&d_S16[(size_t)g * 256 + chalf * 128 + 2 * c2];
                vb = *(const unsigned*)&d_Y16[(size_t)g * 128 + 2 * c2];
            }
            *(unsigned*)&A_s[i_loc][2 * c2] = va;
            *(unsigned*)&B_s[i_loc][2 * c2] = vb;
        }
        __syncthreads();
#pragma unroll
        for (int t = 0; t < 2; t++) {
            int krA = t * 16 + (lane & 7) + ((lane >> 4) << 3);
            unsigned aaddr = shaddr(&A_s[krA][m_base + ((lane >> 3) & 1) * 8]);
            unsigned afrag[2][4];
            ldsm4t(afrag[0], aaddr);
            ldsm4t(afrag[1], aaddr + 32);
            int krB = t * 16 + (lane & 7) + (lane & 8);
            unsigned baddr = shaddr(&B_s[krB][f_basew + ((lane >> 4) & 1) * 8]);
            unsigned bfrag[4][4];
#pragma unroll
            for (int gq = 0; gq < 4; gq++)
                ldsm4t(bfrag[gq], baddr + gq * 32);
#pragma unroll
            for (int p = 0; p < 2; p++)
#pragma unroll
                for (int q = 0; q < 8; q++)
                    mma16816(acc[p][q], afrag[p], &bfrag[q >> 1][(q & 1) * 2]);
        }
    }

    int r    = lane >> 2;
    int col2 = (lane & 3) * 2;
#pragma unroll
    for (int p = 0; p < 2; p++) {
#pragma unroll
        for (int q = 0; q < 8; q++) {
            int cg = chalf * 128 + m_base + p * 16 + r;
            int f  = f_basew + q * 8 + col2;
            float* p0 = &d_pooled[(size_t)cg * FOU1 + f];
            float* p1 = &d_pooled[(size_t)(cg + 8) * FOU1 + f];
            asm volatile("red.global.add.v2.f32 [%0], {%1,%2};"
                         :: "l"(p0), "f"(acc[p][q][0]), "f"(acc[p][q][1]) : "memory");
            asm volatile("red.global.add.v2.f32 [%0], {%1,%2};"
                         :: "l"(p1), "f"(acc[p][q][2]), "f"(acc[p][q][3]) : "memory");
        }
    }
}

// ---------------- K5: edge SDDMM on fp8 residuals + exact sum of coefficients ----------------
__global__ __launch_bounds__(256) void k5_edge(const int* __restrict__ ei,
                                               const float* __restrict__ w, int e) {
    __shared__ float redr[8];
    __shared__ float redc[8];
    int lane = threadIdx.x & 31;
    int wid  = threadIdx.x >> 5;
    int gw = blockIdx.x * 8 + wid;
    int tw = gridDim.x * 8;
    float accr = 0.f;   // sum c_e * <128 r_i, 128 r_j>
    float accc = 0.f;   // 32 * sum c_e (every lane adds)
    for (int j = gw; j < e; j += tw) {
        int s = ei[j];
        int d = ei[e + j];
        float ds = d_deg[s], dd = d_deg[d];
        float c = w[j];
        c = (ds > 0.f) ? c * rsqrtf(ds) : 0.f;
        c = (dd > 0.f) ? c * rsqrtf(dd) : 0.f;
        const uint2* ps = (const uint2*)(&d_R8[(size_t)s * 256]);
        const uint2* pd = (const uint2*)(&d_R8[(size_t)d * 256]);
        uint2 ua = ps[lane];
        uint2 ub = pd[lane];
        const unsigned short* pa = (const unsigned short*)&ua;
        const unsigned short* pb = (const unsigned short*)&ub;
        float dot = 0.f;
#pragma unroll
        for (int q = 0; q < 4; q++) {
            __half2_raw a2 = __nv_cvt_fp8x2_to_halfraw2((__nv_fp8x2_storage_t)pa[q], __NV_E4M3);
            __half2_raw b2 = __nv_cvt_fp8x2_to_halfraw2((__nv_fp8x2_storage_t)pb[q], __NV_E4M3);
            float2 fa = __half22float2(*(__half2*)&a2);
            float2 fb = __half22float2(*(__half2*)&b2);
            dot = fmaf(fa.x, fb.x, dot);
            dot = fmaf(fa.y, fb.y, dot);
        }
        accr = fmaf(c, dot, accr);
        accc += c;
    }
#pragma unroll
    for (int o = 16; o > 0; o >>= 1) {
        accr += __shfl_xor_sync(0xffffffffu, accr, o);
        accc += __shfl_xor_sync(0xffffffffu, accc, o);
    }
    if (lane == 0) { redr[wid] = accr; redc[wid] = accc * (1.0f / 32.0f); }
    __syncthreads();
    if (threadIdx.x == 0) {
        float tr = 0.f, tc = 0.f;
        for (int k = 0; k < 8; k++) { tr += redr[k]; tc += redc[k]; }
        atomicAdd(&d_scal[1], tr);
        atomicAdd(&d_scal[2], tc);
    }
}

// ---------------- K5b: mw = mean_h @ W2e + b2e ----------------
__global__ void k_mw(const float* __restrict__ W2e, const float* __restrict__ b2e) {
    int k = threadIdx.x;
    float acc = b2e[k];
    for (int f = 0; f < FOU1; f++)
        acc = fmaf(d_ysum[f] * (1.0f / 256.0f), W2e[f * 256 + k], acc);
    d_mw[k] = acc;
}

// ---------------- K6: g[k] = sum_c relu(mw[k] + pooled[c] . R2e[:,k]) ----------------
__global__ __launch_bounds__(256) void k6_y2(const float* __restrict__ R2e) {
    __shared__ float prow[FOU1];
    int c = blockIdx.x;
    if (threadIdx.x < FOU1) prow[threadIdx.x] = d_pooled[c * FOU1 + threadIdx.x];
    __syncthreads();
    int k = threadIdx.x;
    float acc = d_mw[k];
#pragma unroll 4
    for (int f = 0; f < FOU1; f++)
        acc = fmaf(prow[f], R2e[f * 256 + k], acc);
    acc = fmaxf(acc, 0.f);
    atomicAdd(&d_g[k], acc);
}

// ---------------- K7: MLP head + log_softmax + reg1 ----------------
__global__ __launch_bounds__(256) void k7_final(
    const float* __restrict__ Wl1, const float* __restrict__ bl1,
    const float* __restrict__ Wl2, const float* __restrict__ bl2,
    float* __restrict__ out, int n, int out_size) {
    __shared__ float gsh[FOU2];
    __shared__ float h1[HLIN];
    __shared__ float lg[OUTP];
    int t = threadIdx.x;
    gsh[t] = d_g[t];
    __syncthreads();
    float acc = bl1[t];
    for (int k = 0; k < FOU2; k++) acc = fmaf(gsh[k], Wl1[k * HLIN + t], acc);
    h1[t] = fmaxf(acc, 0.f);
    __syncthreads();
    if (t < OUTP) {
        float a2 = bl2[t];
        for (int j = 0; j < HLIN; j++) a2 = fmaf(h1[j], Wl2[j * OUTP + t], a2);
        lg[t] = a2;
    }
    __syncthreads();
    if (t == 0) {
        float m = lg[0];
        for (int o = 1; o < OUTP; o++) m = fmaxf(m, lg[o]);
        float s = 0.f;
        for (int o = 0; o < OUTP; o++) s += expf(lg[o] - m);
        float lse = m + logf(s);
        for (int o = 0; o < OUTP; o++) out[o] = lg[o] - lse;
        if (out_size > OUTP) {
            // edge term = edge_c/256 + edge_r ; stored residual dot is scaled by 128*128
            float edge = d_scal[2] * 0.00390625f + d_scal[1] * (1.0f / 16384.0f);
            out[OUTP] = (d_scal[0] - edge) / (float)n;
        }
    }
}

// ---------------- launch ----------------
extern "C" void kernel_launch(void* const* d_in, const int* in_sizes, int n_in,
                              void* d_out, int out_size) {
    const float* x   = (const float*)d_in[0];
    const int*   ei  = (const int*)d_in[1];
    const float* wht = (const float*)d_in[2];
    const float* W1p = (const float*)d_in[3];
    const float* R1p = (const float*)d_in[4];
    const float* b1p = (const float*)d_in[5];
    const float* W1e = (const float*)d_in[6];
    const float* R1e = (const float*)d_in[7];
    const float* b1e = (const float*)d_in[8];
    // d_in[9..11] = W2p, R2p, b2p: dead code (softmax over size-1 axis == 1)
    const float* W2e = (const float*)d_in[12];
    const float* R2e = (const float*)d_in[13];
    const float* b2e = (const float*)d_in[14];
    const float* Wl1 = (const float*)d_in[15];
    const float* bl1 = (const float*)d_in[16];
    const float* Wl2 = (const float*)d_in[17];
    const float* bl2 = (const float*)d_in[18];

    int n = in_sizes[0] / 5;
    int e = in_sizes[2];

    k0_zero<<<512, 256>>>(n);
    k1_edge_agg<<<(e + 255) / 256, 256>>>(x, ei, wht, n, e);
    k2_node<<<592, 256>>>(x, W1p, R1p, b1p, W1e, R1e, b1e, n);
    k3_pool<<<2 * KSPLIT, 256>>>(n);
    k5_edge<<<1184, 256>>>(ei, wht, e);
    k_mw<<<1, 256>>>(W2e, b2e);
    k6_y2<<<CLUS, 256>>>(R2e);
    k7_final<<<1, 256>>>(Wl1, bl1, Wl2, bl2, (float*)d_out, n, out_size);
}

// round 4
// speedup vs baseline: 2.8391x; 1.3272x over previous
#include <cuda_runtime.h>
#include <cuda_fp16.h>

#define NMAX 50000
#define EMAX 800000
#define CLUS 256
#define FOU1 128
#define FOU2 256
#define HLIN 256
#define OUTP 10
#define KSPLIT 148

// ---------------- static scratch ----------------
__device__ __align__(32) float d_agg[NMAX * 8];         // [0..4]=sum x[src], [5]=cnt
__device__ __align__(32) float d_x8[NMAX * 8];          // padded copy of x
__device__ float  d_deg[NMAX];                          // weighted out-degree (src)
__device__ __half d_S16[(size_t)NMAX * CLUS];           // softmax S, fp16 (GEMM)
__device__ char   d_Q8[(size_t)NMAX * CLUS];            // int8 of (S-1/256)*srow
__device__ float2 d_aux[NMAX];                          // {rsqrt(deg) or 0, row inv-scale}
__device__ __half d_Y16[(size_t)NMAX * FOU1];           // relu features, fp16
__device__ float  d_pooled[CLUS * FOU1];                // atomically accumulated
__device__ float  d_ysum[FOU1];                         // sum_i Y[i]
__device__ float  d_g[FOU2];                            // sum_c y2[c]
__device__ float  d_scal[3];                            // [0]=diag, [1]=edge residual, [2]=sum c_e

// ---------------- K0: zero accumulators + pad x ----------------
__global__ void k0_zero(const float* __restrict__ x, int n) {
    int tot = n * 8 + n * 8 + n + CLUS * FOU1 + FOU1 + FOU2 + 3;
    for (int i = blockIdx.x * blockDim.x + threadIdx.x; i < tot;
         i += gridDim.x * blockDim.x) {
        int j = i;
        if (j < n * 8)       { d_agg[j] = 0.f; continue; } j -= n * 8;
        if (j < n * 8)       { int k = j & 7;
                               d_x8[j] = (k < 5) ? x[(j >> 3) * 5 + k] : 0.f; continue; } j -= n * 8;
        if (j < n)           { d_deg[j]    = 0.f; continue; } j -= n;
        if (j < CLUS * FOU1) { d_pooled[j] = 0.f; continue; } j -= CLUS * FOU1;
        if (j < FOU1)        { d_ysum[j]   = 0.f; continue; } j -= FOU1;
        if (j < FOU2)        { d_g[j]      = 0.f; continue; } j -= FOU2;
        d_scal[j] = 0.f;
    }
}

// ---------------- K1: edge aggregation (vector gather + vector red) ----------------
__global__ void k1_edge_agg(const int* __restrict__ ei, const float* __restrict__ w,
                            int n, int e) {
    for (int j = blockIdx.x * blockDim.x + threadIdx.x; j < e;
         j += gridDim.x * blockDim.x) {
        int s = ei[j];
        int d = ei[e + j];
        float wv = w[j];
        float4 v0 = *(const float4*)&d_x8[(size_t)s * 8];
        float  v4 = d_x8[(size_t)s * 8 + 4];
        float* base = &d_agg[(size_t)d * 8];
        float one = 1.0f;
        asm volatile("red.global.add.v4.f32 [%0], {%1,%2,%3,%4};"
                     :: "l"(base), "f"(v0.x), "f"(v0.y), "f"(v0.z), "f"(v0.w) : "memory");
        asm volatile("red.global.add.v2.f32 [%0], {%1,%2};"
                     :: "l"(base + 4), "f"(v4), "f"(one) : "memory");
        atomicAdd(&d_deg[s], wv);
    }
}

// ---------------- K2: conv -> softmax S (fp16 + int8 residual w/ row scale) / relu Y ----------------
__global__ __launch_bounds__(256) void k2_node(
    const float* __restrict__ x,
    const float* __restrict__ W1p, const float* __restrict__ R1p, const float* __restrict__ b1p,
    const float* __restrict__ W1e, const float* __restrict__ R1e, const float* __restrict__ b1e,
    int n) {
    __shared__ float ysh[FOU1];
    __shared__ float red[8];
    for (int t = threadIdx.x; t < FOU1; t += blockDim.x) ysh[t] = 0.f;
    __syncthreads();

    int lane = threadIdx.x & 31;
    int wid  = threadIdx.x >> 5;
    int warpsTotal = gridDim.x * 8;
    int gw = blockIdx.x * 8 + wid;

    float yloc[4] = {0.f, 0.f, 0.f, 0.f};
    float dacc = 0.f;

    for (int i = gw; i < n; i += warpsTotal) {
        float xv = 0.f, av = 0.f;
        if (lane < 5) { xv = x[i * 5 + lane]; }
        if (lane < 6) { av = d_agg[(size_t)i * 8 + lane]; }
        float cv   = __shfl_sync(0xffffffffu, av, 5);
        float degv = d_deg[i];
        float denom = fmaxf(cv, 1.0f);
        float xa[5], aa[5];
#pragma unroll
        for (int k = 0; k < 5; k++) {
            xa[k] = __shfl_sync(0xffffffffu, xv, k);
            aa[k] = __shfl_sync(0xffffffffu, av, k) / denom;
        }
        float sv[8];
#pragma unroll
        for (int j = 0; j < 8; j++) {
            int c = j * 32 + lane;
            float acc = b1p[c];
#pragma unroll
            for (int k = 0; k < 5; k++) {
                acc = fmaf(aa[k], W1p[k * 256 + c], acc);
                acc = fmaf(xa[k], R1p[k * 256 + c], acc);
            }
            sv[j] = acc;
        }
        float m = sv[0];
#pragma unroll
        for (int j = 1; j < 8; j++) m = fmaxf(m, sv[j]);
#pragma unroll
        for (int o = 16; o > 0; o >>= 1) m = fmaxf(m, __shfl_xor_sync(0xffffffffu, m, o));
        float sum = 0.f, ev[8];
#pragma unroll
        for (int j = 0; j < 8; j++) { ev[j] = __expf(sv[j] - m); sum += ev[j]; }
#pragma unroll
        for (int o = 16; o > 0; o >>= 1) sum += __shfl_xor_sync(0xffffffffu, sum, o);
        float inv = 1.0f / sum;
        float sq = 0.f;
        float rr[8];
        float maxr = 0.f;
#pragma unroll
        for (int j = 0; j < 8; j++) {
            float p = ev[j] * inv;
            d_S16[(size_t)i * 256 + j * 32 + lane] = __float2half_rn(p);
            rr[j] = p - 0.00390625f;
            maxr = fmaxf(maxr, fabsf(rr[j]));
            sq = fmaf(p, p, sq);
        }
#pragma unroll
        for (int o = 16; o > 0; o >>= 1) maxr = fmaxf(maxr, __shfl_xor_sync(0xffffffffu, maxr, o));
        float srow   = (maxr > 0.f) ? 127.0f / maxr : 0.f;
        float invrow = maxr * (1.0f / 127.0f);
#pragma unroll
        for (int j = 0; j < 8; j++) {
            int q = __float2int_rn(rr[j] * srow);
            d_Q8[(size_t)i * 256 + j * 32 + lane] = (char)q;
        }
        if (lane == 0) {
            float isq = (degv > 0.f) ? rsqrtf(degv) : 0.f;
            d_aux[i] = make_float2(isq, invrow);
        }
        if (degv > 0.f) dacc += sq;
#pragma unroll
        for (int j = 0; j < 4; j++) {
            int c = j * 32 + lane;
            float acc = b1e[c];
#pragma unroll
            for (int k = 0; k < 5; k++) {
                acc = fmaf(aa[k], W1e[k * 128 + c], acc);
                acc = fmaf(xa[k], R1e[k * 128 + c], acc);
            }
            acc = fmaxf(acc, 0.f);
            d_Y16[(size_t)i * 128 + c] = __float2half_rn(acc);
            yloc[j] += acc;
        }
    }
#pragma unroll
    for (int o = 16; o > 0; o >>= 1) dacc += __shfl_xor_sync(0xffffffffu, dacc, o);
    if (lane == 0) red[wid] = dacc;
#pragma unroll
    for (int j = 0; j < 4; j++) atomicAdd(&ysh[j * 32 + lane], yloc[j]);
    __syncthreads();
    if (threadIdx.x == 0) {
        float t = 0.f;
        for (int k = 0; k < 8; k++) t += red[k];
        atomicAdd(&d_scal[0], t);
    }
    if (threadIdx.x < FOU1) atomicAdd(&d_ysum[threadIdx.x], ysh[threadIdx.x]);
}

// ---------------- K3: pooled += S^T Y via mma.sync m16n8k16, atomic epilogue ----------------
#define CHUNK 32
#define APITCH 136

__device__ __forceinline__ unsigned shaddr(const void* p) {
    return (unsigned)__cvta_generic_to_shared(p);
}
__device__ __forceinline__ void ldsm4t(unsigned* r, unsigned addr) {
    asm volatile("ldmatrix.sync.aligned.m8n8.x4.trans.shared.b16 {%0,%1,%2,%3}, [%4];"
                 : "=r"(r[0]), "=r"(r[1]), "=r"(r[2]), "=r"(r[3]) : "r"(addr));
}
__device__ __forceinline__ void mma16816(float* c, const unsigned* a, const unsigned* b) {
    asm volatile("mma.sync.aligned.m16n8k16.row.col.f32.f16.f16.f32 "
                 "{%0,%1,%2,%3}, {%4,%5,%6,%7}, {%8,%9}, {%0,%1,%2,%3};"
                 : "+f"(c[0]), "+f"(c[1]), "+f"(c[2]), "+f"(c[3])
                 : "r"(a[0]), "r"(a[1]), "r"(a[2]), "r"(a[3]), "r"(b[0]), "r"(b[1]));
}

__global__ __launch_bounds__(256) void k3_pool(int n) {
    __shared__ __align__(16) __half A_s[CHUNK][APITCH];
    __shared__ __align__(16) __half B_s[CHUNK][APITCH];
    int b     = blockIdx.x;
    int chalf = b & 1;
    int kb    = b >> 1;
    int per   = (n + KSPLIT - 1) / KSPLIT;
    int lo    = kb * per;
    int hi    = min(n, lo + per);

    int tid  = threadIdx.x;
    int lane = tid & 31;
    int wid  = tid >> 5;
    int m_base  = (wid >> 1) * 32;
    int f_basew = (wid & 1) * 64;

    float acc[2][8][4];
#pragma unroll
    for (int p = 0; p < 2; p++)
#pragma unroll
        for (int q = 0; q < 8; q++)
#pragma unroll
            for (int v = 0; v < 4; v++) acc[p][q][v] = 0.f;

    for (int i0 = lo; i0 < hi; i0 += CHUNK) {
        __syncthreads();
#pragma unroll
        for (int rep = 0; rep < 8; rep++) {
            int e2    = rep * 256 + tid;
            int i_loc = e2 >> 6;
            int c2    = e2 & 63;
            int g     = i0 + i_loc;
            unsigned va = 0u, vb = 0u;
            if (g < hi) {
                va = *(const unsigned*)&d_S16[(size_t)g * 256 + chalf * 128 + 2 * c2];
                vb = *(const unsigned*)&d_Y16[(size_t)g * 128 + 2 * c2];
            }
            *(unsigned*)&A_s[i_loc][2 * c2] = va;
            *(unsigned*)&B_s[i_loc][2 * c2] = vb;
        }
        __syncthreads();
#pragma unroll
        for (int t = 0; t < 2; t++) {
            int krA = t * 16 + (lane & 7) + ((lane >> 4) << 3);
            unsigned aaddr = shaddr(&A_s[krA][m_base + ((lane >> 3) & 1) * 8]);
            unsigned afrag[2][4];
            ldsm4t(afrag[0], aaddr);
            ldsm4t(afrag[1], aaddr + 32);
            int krB = t * 16 + (lane & 7) + (lane & 8);
            unsigned baddr = shaddr(&B_s[krB][f_basew + ((lane >> 4) & 1) * 8]);
            unsigned bfrag[4][4];
#pragma unroll
            for (int gq = 0; gq < 4; gq++)
                ldsm4t(bfrag[gq], baddr + gq * 32);
#pragma unroll
            for (int p = 0; p < 2; p++)
#pragma unroll
                for (int q = 0; q < 8; q++)
                    mma16816(acc[p][q], afrag[p], &bfrag[q >> 1][(q & 1) * 2]);
        }
    }

    int r    = lane >> 2;
    int col2 = (lane & 3) * 2;
#pragma unroll
    for (int p = 0; p < 2; p++) {
#pragma unroll
        for (int q = 0; q < 8; q++) {
            int cg = chalf * 128 + m_base + p * 16 + r;
            int f  = f_basew + q * 8 + col2;
            float* p0 = &d_pooled[(size_t)cg * FOU1 + f];
            float* p1 = &d_pooled[(size_t)(cg + 8) * FOU1 + f];
            asm volatile("red.global.add.v2.f32 [%0], {%1,%2};"
                         :: "l"(p0), "f"(acc[p][q][0]), "f"(acc[p][q][1]) : "memory");
            asm volatile("red.global.add.v2.f32 [%0], {%1,%2};"
                         :: "l"(p1), "f"(acc[p][q][2]), "f"(acc[p][q][3]) : "memory");
        }
    }
}

// ---------------- K5: edge SDDMM, 2 edges/warp, int8 DP4A, per-lane scaled acc ----------------
__global__ __launch_bounds__(256) void k5_edge(const int* __restrict__ ei,
                                               const float* __restrict__ w, int e) {
    __shared__ float redr[8];
    __shared__ float redc[8];
    int lane = threadIdx.x & 31;
    int sub  = lane & 15;
    int half = lane >> 4;
    int wid  = threadIdx.x >> 5;
    int gw = blockIdx.x * 8 + wid;
    int tw = gridDim.x * 8;
    float accr = 0.f;   // sum c_e * <r_i, r_j>  (scales folded in)
    float accc = 0.f;   // 16 * sum c_e
#pragma unroll 2
    for (int j = 2 * gw + half; j < e; j += 2 * tw) {
        int s = ei[j];
        int d = ei[e + j];
        float wv = w[j];
        float2 as = d_aux[s];
        float2 ad = d_aux[d];
        float csc = wv * as.x * ad.x;
        float scl = csc * as.y * ad.y;
        const int4* ps = (const int4*)&d_Q8[(size_t)s * 256];
        const int4* pd = (const int4*)&d_Q8[(size_t)d * 256];
        int4 a = ps[sub];
        int4 b = pd[sub];
        int id = __dp4a(a.x, b.x, __dp4a(a.y, b.y, __dp4a(a.z, b.z, __dp4a(a.w, b.w, 0))));
        accr = fmaf(scl, (float)id, accr);
        accc += csc;
    }
#pragma unroll
    for (int o = 16; o > 0; o >>= 1) {
        accr += __shfl_xor_sync(0xffffffffu, accr, o);
        accc += __shfl_xor_sync(0xffffffffu, accc, o);
    }
    if (lane == 0) { redr[wid] = accr; redc[wid] = accc * (1.0f / 16.0f); }
    __syncthreads();
    if (threadIdx.x == 0) {
        float tr = 0.f, tc = 0.f;
        for (int k = 0; k < 8; k++) { tr += redr[k]; tc += redc[k]; }
        atomicAdd(&d_scal[1], tr);
        atomicAdd(&d_scal[2], tc);
    }
}

// ---------------- K6: g[k] += relu(mw[k] + pooled[c] . R2e[:,k])  (mw recomputed) ----------------
__global__ __launch_bounds__(256) void k6_y2(const float* __restrict__ R2e,
                                             const float* __restrict__ W2e,
                                             const float* __restrict__ b2e) {
    __shared__ float prow[FOU1];
    __shared__ float ys[FOU1];
    int c = blockIdx.x;
    if (threadIdx.x < FOU1) {
        prow[threadIdx.x] = d_pooled[c * FOU1 + threadIdx.x];
        ys[threadIdx.x]   = d_ysum[threadIdx.x] * (1.0f / 256.0f);
    }
    __syncthreads();
    int k = threadIdx.x;
    float acc = b2e[k];
#pragma unroll 4
    for (int f = 0; f < FOU1; f++) {
        acc = fmaf(ys[f],   W2e[f * 256 + k], acc);
        acc = fmaf(prow[f], R2e[f * 256 + k], acc);
    }
    acc = fmaxf(acc, 0.f);
    atomicAdd(&d_g[k], acc);
}

// ---------------- K7: MLP head + log_softmax + reg1 ----------------
__global__ __launch_bounds__(256) void k7_final(
    const float* __restrict__ Wl1, const float* __restrict__ bl1,
    const float* __restrict__ Wl2, const float* __restrict__ bl2,
    float* __restrict__ out, int n, int out_size) {
    __shared__ float gsh[FOU2];
    __shared__ float h1[HLIN];
    __shared__ float lg[OUTP];
    int t = threadIdx.x;
    gsh[t] = d_g[t];
    __syncthreads();
    float acc = bl1[t];
    for (int k = 0; k < FOU2; k++) acc = fmaf(gsh[k], Wl1[k * HLIN + t], acc);
    h1[t] = fmaxf(acc, 0.f);
    __syncthreads();
    if (t < OUTP) {
        float a2 = bl2[t];
        for (int j = 0; j < HLIN; j++) a2 = fmaf(h1[j], Wl2[j * OUTP + t], a2);
        lg[t] = a2;
    }
    __syncthreads();
    if (t == 0) {
        float m = lg[0];
        for (int o = 1; o < OUTP; o++) m = fmaxf(m, lg[o]);
        float s = 0.f;
        for (int o = 0; o < OUTP; o++) s += expf(lg[o] - m);
        float lse = m + logf(s);
        for (int o = 0; o < OUTP; o++) out[o] = lg[o] - lse;
        if (out_size > OUTP) {
            float edge = d_scal[2] * 0.00390625f + d_scal[1];
            out[OUTP] = (d_scal[0] - edge) / (float)n;
        }
    }
}

// ---------------- launch ----------------
extern "C" void kernel_launch(void* const* d_in, const int* in_sizes, int n_in,
                              void* d_out, int out_size) {
    const float* x   = (const float*)d_in[0];
    const int*   ei  = (const int*)d_in[1];
    const float* wht = (const float*)d_in[2];
    const float* W1p = (const float*)d_in[3];
    const float* R1p = (const float*)d_in[4];
    const float* b1p = (const float*)d_in[5];
    const float* W1e = (const float*)d_in[6];
    const float* R1e = (const float*)d_in[7];
    const float* b1e = (const float*)d_in[8];
    // d_in[9..11] = W2p, R2p, b2p: dead (softmax over size-1 axis == 1)
    const float* W2e = (const float*)d_in[12];
    const float* R2e = (const float*)d_in[13];
    const float* b2e = (const float*)d_in[14];
    const float* Wl1 = (const float*)d_in[15];
    const float* bl1 = (const float*)d_in[16];
    const float* Wl2 = (const float*)d_in[17];
    const float* bl2 = (const float*)d_in[18];

    int n = in_sizes[0] / 5;
    int e = in_sizes[2];

    k0_zero<<<512, 256>>>(x, n);
    k1_edge_agg<<<(e + 255) / 256, 256>>>(ei, wht, n, e);
    k2_node<<<592, 256>>>(x, W1p, R1p, b1p, W1e, R1e, b1e, n);
    k3_pool<<<2 * KSPLIT, 256>>>(n);
    k5_edge<<<1184, 256>>>(ei, wht, e);
    k6_y2<<<CLUS, 256>>>(R2e, W2e, b2e);
    k7_final<<<1, 256>>>(Wl1, bl1, Wl2, bl2, (float*)d_out, n, out_size);
}